// round 9
// baseline (speedup 1.0000x reference)
#include <cuda_runtime.h>
#include <math.h>

#define HID   2048
#define INTER 8192
#define QKV   8192
#define TV    4096
#define NVH   32
#define KD    128
#define VD    128
#define NKH   16
#define CK    4

// ---------------- scratch (device globals; no allocations allowed) ----------
__device__ float g_proj[QKV + TV + 2*NVH]; // in_proj output (z/a/b part used)
__device__ float g_conv[QKV];              // silu(conv) output
__device__ float g_ygated[TV];             // gated per-head outputs
__device__ float g_x1[HID];                // residual + attn_out
__device__ float g_inter[INTER];           // silu(gate)*up

__device__ __forceinline__ void pdl_wait()    { asm volatile("griddepcontrol.wait;" ::: "memory"); }
__device__ __forceinline__ void pdl_trigger() { asm volatile("griddepcontrol.launch_dependents;" ::: "memory"); }

__device__ __forceinline__ float warp_sum(float v) {
#pragma unroll
    for (int o = 16; o; o >>= 1) v += __shfl_down_sync(0xffffffffu, v, o);
    return v;
}

__device__ __forceinline__ float silu(float x) { return x / (1.f + expf(-x)); }

__device__ __forceinline__ float dot4(float4 a, float4 b) {
    return a.x * b.x + a.y * b.y + a.z * b.z + a.w * b.w;
}
__device__ __forceinline__ float sq4(float4 a) {
    return a.x * a.x + a.y * a.y + a.z * a.z + a.w * a.w;
}

// block-wide sum (128 threads), result broadcast to all threads
__device__ __forceinline__ float block_sum_bcast128(float s, float* red) {
    s = warp_sum(s);
    if ((threadIdx.x & 31) == 0) red[threadIdx.x >> 5] = s;
    __syncthreads();
    return red[0] + red[1] + red[2] + red[3];
}

// ---------------- in_proj with fused input rmsnorm + conv update -----------
// 2 rows/block, 128 threads. dot(W_row, rmsnorm(x)*(1+ln)) = inv*dot(W_row, x*(1+ln))
__global__ void __launch_bounds__(128) inproj_fused_k(
        const float* __restrict__ W, const float* __restrict__ x,
        const float* __restrict__ ln, const float* __restrict__ cs,
        const float* __restrict__ cw, float* __restrict__ out_conv_state) {
    __shared__ float red[4], red0[4], red1[4];
    int r0 = blockIdx.x * 2, r1 = r0 + 1;
    const float4* W0 = (const float4*)(W + (size_t)r0 * HID);
    const float4* W1 = (const float4*)(W + (size_t)r1 * HID);
    float4 a0[4], a1[4];
#pragma unroll
    for (int i = 0; i < 4; i++) {
        a0[i] = __ldcs(W0 + threadIdx.x + 128 * i);
        a1[i] = __ldcs(W1 + threadIdx.x + 128 * i);
    }
    pdl_wait();  // first kernel: trivially satisfied
    const float4* x4 = (const float4*)x;
    const float4* l4 = (const float4*)ln;
    float4 t[4];
    float ss = 0.f;
#pragma unroll
    for (int i = 0; i < 4; i++) {
        float4 xv = __ldg(&x4[threadIdx.x + 128 * i]);
        float4 lv = __ldg(&l4[threadIdx.x + 128 * i]);
        ss += sq4(xv);
        t[i] = make_float4(xv.x * (1.f + lv.x), xv.y * (1.f + lv.y),
                           xv.z * (1.f + lv.z), xv.w * (1.f + lv.w));
    }
    float tot_ss = block_sum_bcast128(ss, red);
    float inv = rsqrtf(tot_ss / HID + 1e-6f);
    float s0 = 0.f, s1 = 0.f;
#pragma unroll
    for (int i = 0; i < 4; i++) { s0 += dot4(a0[i], t[i]); s1 += dot4(a1[i], t[i]); }
    s0 = warp_sum(s0);
    s1 = warp_sum(s1);
    if ((threadIdx.x & 31) == 0) { red0[threadIdx.x >> 5] = s0; red1[threadIdx.x >> 5] = s1; }
    __syncthreads();
    if (threadIdx.x < 2) {
        int r = threadIdx.x ? r1 : r0;
        float* red_ = threadIdx.x ? red1 : red0;
        float tot = (red_[0] + red_[1] + red_[2] + red_[3]) * inv;
        g_proj[r] = tot;
        if (r < QKV) {
            float c1 = cs[r * 4 + 1], c2 = cs[r * 4 + 2], c3 = cs[r * 4 + 3];
            float4 w4 = ((const float4*)cw)[r];
            float acc = c1 * w4.x + c2 * w4.y + c3 * w4.z + tot * w4.w;
            ((float4*)out_conv_state)[r] = make_float4(c1, c2, c3, tot);
            g_conv[r] = silu(acc);
        }
    }
    pdl_trigger();
}

// ---------------- block-per-row matvec, IT front-batched loads -------------
template <int K, int TPB, bool RES>
__global__ void __launch_bounds__(TPB) rowmv_k(
        const float* __restrict__ W, const float* __restrict__ v,
        const float* __restrict__ res, float* __restrict__ y) {
    constexpr int IT = K / 4 / TPB;
    __shared__ float red[TPB / 32];
    int r = blockIdx.x;
    const float4* Wr = (const float4*)(W + (size_t)r * K);
    float4 a[IT];
#pragma unroll
    for (int i = 0; i < IT; i++) a[i] = __ldcs(Wr + threadIdx.x + TPB * i);
    pdl_wait();
    const float4* v4 = (const float4*)v;
    float s = 0.f;
#pragma unroll
    for (int i = 0; i < IT; i++) s += dot4(a[i], __ldg(&v4[threadIdx.x + TPB * i]));
    s = warp_sum(s);
    if ((threadIdx.x & 31) == 0) red[threadIdx.x >> 5] = s;
    __syncthreads();
    if (threadIdx.x == 0) {
        float t = 0.f;
#pragma unroll
        for (int i = 0; i < TPB / 32; i++) t += red[i];
        y[r] = RES ? (res[r] + t) : t;
    }
    pdl_trigger();
}

// ---------------- gate/up with fused post rmsnorm --------------------------
// 1 row of each of G and U per block, 128 threads.
__global__ void __launch_bounds__(128) gateup_fused_k(
        const float* __restrict__ G, const float* __restrict__ U,
        const float* __restrict__ pw) {
    __shared__ float red[4], redg[4], redu[4];
    int r = blockIdx.x;
    const float4* g4 = (const float4*)(G + (size_t)r * HID);
    const float4* u4 = (const float4*)(U + (size_t)r * HID);
    float4 ag[4], au[4];
#pragma unroll
    for (int i = 0; i < 4; i++) {
        ag[i] = __ldcs(g4 + threadIdx.x + 128 * i);
        au[i] = __ldcs(u4 + threadIdx.x + 128 * i);
    }
    pdl_wait();
    const float4* x4 = (const float4*)g_x1;
    const float4* p4 = (const float4*)pw;
    float4 t[4];
    float ss = 0.f;
#pragma unroll
    for (int i = 0; i < 4; i++) {
        float4 xv = __ldg(&x4[threadIdx.x + 128 * i]);
        float4 pv = __ldg(&p4[threadIdx.x + 128 * i]);
        ss += sq4(xv);
        t[i] = make_float4(xv.x * (1.f + pv.x), xv.y * (1.f + pv.y),
                           xv.z * (1.f + pv.z), xv.w * (1.f + pv.w));
    }
    float tot_ss = block_sum_bcast128(ss, red);
    float inv = rsqrtf(tot_ss / HID + 1e-6f);
    float sg = 0.f, su = 0.f;
#pragma unroll
    for (int i = 0; i < 4; i++) { sg += dot4(ag[i], t[i]); su += dot4(au[i], t[i]); }
    sg = warp_sum(sg);
    su = warp_sum(su);
    if ((threadIdx.x & 31) == 0) { redg[threadIdx.x >> 5] = sg; redu[threadIdx.x >> 5] = su; }
    __syncthreads();
    if (threadIdx.x == 0) {
        float tg = (redg[0] + redg[1] + redg[2] + redg[3]) * inv;
        float tu = (redu[0] + redu[1] + redu[2] + redu[3]) * inv;
        g_inter[r] = silu(tg) * tu;
    }
    pdl_trigger();
}

// ---------------- delta rule per head + gated rmsnorm ----------------------
// block = 1 head, 1024 threads. S staged to SMEM before pdl_wait (overlap).
__global__ void delta_k(const float* __restrict__ Sin, const float* __restrict__ A_log,
                        const float* __restrict__ dt_bias, const float* __restrict__ norm_w,
                        float* __restrict__ Sout) {
    extern __shared__ float sm[];
    float* Ssh  = sm;                    // 16384
    float* kn   = sm + KD * VD;          // 128
    float* qn   = kn + KD;               // 128
    float* dl   = qn + KD;               // 128
    float* part = dl + KD;               // 1024
    float* red  = part + 1024;           // 4

    int h   = blockIdx.x;
    int tid = threadIdx.x;
    int t   = tid & 127;
    int kg  = tid >> 7;
    int kh  = h >> 1;  // RATIO = 2

    // stage S (independent of previous kernel) BEFORE the PDL wait
    const float4* S4 = (const float4*)(Sin + (size_t)h * KD * VD);
#pragma unroll
    for (int i = 0; i < 4; i++)
        ((float4*)Ssh)[tid + 1024 * i] = S4[tid + 1024 * i];

    pdl_wait();

    float qv = 0.f, kv = 0.f, vv = 0.f;
    if (tid < 128) {
        qv = g_conv[kh * KD + t];
        kv = g_conv[NKH * KD + kh * KD + t];
        vv = g_conv[2 * NKH * KD + h * VD + t];
        float s = warp_sum(qv * qv);
        if ((t & 31) == 0) red[t >> 5] = s;
    }
    __syncthreads();
    if (tid < 128) {
        float qs = red[0] + red[1] + red[2] + red[3];
        qn[t] = qv / fmaxf(sqrtf(qs), 1e-12f);
    }
    __syncthreads();
    if (tid < 128) {
        float s = warp_sum(kv * kv);
        if ((t & 31) == 0) red[t >> 5] = s;
    }
    __syncthreads();
    if (tid < 128) {
        float ks = red[0] + red[1] + red[2] + red[3];
        kn[t] = kv / fmaxf(sqrtf(ks), 1e-12f);
    }
    __syncthreads();

    float a = g_proj[QKV + TV + h];
    float b = g_proj[QKV + TV + NVH + h];
    float beta = 1.f / (1.f + expf(-b));
    float spx = a + dt_bias[h];
    float sp = (spx > 20.f) ? spx : log1pf(expf(spx));
    float decay = expf(-expf(A_log[h]) * sp);

    // pass 1: Sk[t] = sum_k S[k,t]*kn[k], k split over 8 groups
    {
        float s = 0.f;
        int k0 = kg * 16;
#pragma unroll
        for (int k = 0; k < 16; k++) s += Ssh[(k0 + k) * VD + t] * kn[k0 + k];
        part[kg * 128 + t] = s;
    }
    __syncthreads();
    if (tid < 128) {
        float sk = 0.f;
#pragma unroll
        for (int g = 0; g < 8; g++) sk += part[g * 128 + t];
        dl[t] = vv - sk;
    }
    __syncthreads();

    // pass 2: newS (write global) + y partials
    float* So = Sout + (size_t)h * KD * VD;
    {
        float del = dl[t];
        float yp = 0.f;
        int k0 = kg * 16;
#pragma unroll
        for (int k = 0; k < 16; k++) {
            int kk = k0 + k;
            float ns = decay * Ssh[kk * VD + t] + beta * kn[kk] * del;
            So[kk * VD + t] = ns;
            yp += ns * qn[kk];
        }
        part[kg * 128 + t] = yp;
    }
    __syncthreads();

    float y = 0.f;
    if (tid < 128) {
#pragma unroll
        for (int g = 0; g < 8; g++) y += part[g * 128 + t];
        float s = warp_sum(y * y);
        if ((t & 31) == 0) red[t >> 5] = s;
    }
    __syncthreads();
    if (tid < 128) {
        float var = (red[0] + red[1] + red[2] + red[3]) / VD;
        float yn = y * rsqrtf(var + 1e-6f) * norm_w[t];
        float z = g_proj[QKV + h * VD + t];
        g_ygated[h * VD + t] = yn * silu(z);
    }
    pdl_trigger();
}

// ---------------- host-side PDL launch helper ------------------------------
template <typename F, typename... Args>
static void launch_pdl(F* func, dim3 grid, dim3 block, size_t smem, Args... args) {
    cudaLaunchAttribute attr[1] = {};
    attr[0].id = cudaLaunchAttributeProgrammaticStreamSerialization;
    attr[0].val.programmaticStreamSerializationAllowed = 1;
    cudaLaunchConfig_t cfg = {};
    cfg.gridDim = grid;
    cfg.blockDim = block;
    cfg.dynamicSmemBytes = smem;
    cfg.stream = 0;
    cfg.attrs = attr;
    cfg.numAttrs = 1;
    cudaLaunchKernelEx(&cfg, func, args...);
}

extern "C" void kernel_launch(void* const* d_in, const int* in_sizes, int n_in,
                              void* d_out, int out_size) {
    const float* x          = (const float*)d_in[0];
    const float* conv_state = (const float*)d_in[1];
    const float* ssm_state  = (const float*)d_in[2];
    const float* in_ln_w    = (const float*)d_in[3];
    const float* in_proj_w  = (const float*)d_in[4];
    const float* conv_w     = (const float*)d_in[5];
    const float* A_log      = (const float*)d_in[6];
    const float* dt_bias    = (const float*)d_in[7];
    const float* norm_w     = (const float*)d_in[8];
    const float* out_proj_w = (const float*)d_in[9];
    const float* post_ln_w  = (const float*)d_in[10];
    const float* gate_w     = (const float*)d_in[11];
    const float* up_w       = (const float*)d_in[12];
    const float* down_w     = (const float*)d_in[13];

    float* out        = (float*)d_out;
    float* out_x      = out;                       // 2048
    float* out_conv   = out + HID;                 // 32768
    float* out_ssm    = out + HID + QKV * CK;      // 524288

    float *p_x1, *p_inter, *p_yg;
    cudaGetSymbolAddress((void**)&p_x1,    g_x1);
    cudaGetSymbolAddress((void**)&p_inter, g_inter);
    cudaGetSymbolAddress((void**)&p_yg,    g_ygated);

    const int ROWS_INPROJ = QKV + TV + 2 * NVH;  // 12352
    const int DELTA_SMEM = (KD * VD + 3 * KD + 1024 + 16) * sizeof(float);  // ~70KB
    cudaFuncSetAttribute(delta_k, cudaFuncAttributeMaxDynamicSharedMemorySize, DELTA_SMEM);

    // 1. proj = in_proj_w @ rmsnorm(x)  (12352 x 2048), fused norm + conv
    launch_pdl(inproj_fused_k, ROWS_INPROJ / 2, 128, 0,
               in_proj_w, x, in_ln_w, conv_state, conv_w, out_conv);
    // 2. per-head delta rule + gated rmsnorm -> g_ygated, new ssm state
    launch_pdl(delta_k, NVH, 1024, (size_t)DELTA_SMEM,
               ssm_state, A_log, dt_bias, norm_w, out_ssm);
    // 3. x1 = x + out_proj_w @ y_gated   (2048 x 4096)
    launch_pdl(rowmv_k<TV, 128, true>, HID, 128, 0,
               out_proj_w, (const float*)p_yg, x, p_x1);
    // 4. inter = silu(gate_w@hn) * (up_w@hn), hn = rmsnorm(x1) fused
    launch_pdl(gateup_fused_k, INTER, 128, 0, gate_w, up_w, post_ln_w);
    // 5. x_out = x1 + down_w @ inter   (2048 x 8192)
    launch_pdl(rowmv_k<INTER, 256, true>, HID, 256, 0,
               down_w, (const float*)p_inter, (const float*)p_x1, out_x);
}

// round 10
// speedup vs baseline: 1.1268x; 1.1268x over previous
#include <cuda_runtime.h>
#include <math.h>

#define HID   2048
#define INTER 8192
#define QKV   8192
#define TV    4096
#define NVH   32
#define KD    128
#define VD    128
#define NKH   16
#define CK    4

// ---------------- scratch (device globals; no allocations allowed) ----------
__device__ float g_h[HID];                 // rmsnorm(x)
__device__ float g_proj[QKV + TV + 2*NVH]; // in_proj output (z/a/b part used)
__device__ float g_conv[QKV];              // silu(conv) output
__device__ float g_ygated[TV];             // gated per-head outputs
__device__ float g_x1[HID];                // residual + attn_out
__device__ float g_hn[HID];                // rmsnorm(x1)
__device__ float g_inter[INTER];           // silu(gate)*up

__device__ __forceinline__ void pdl_wait()    { asm volatile("griddepcontrol.wait;" ::: "memory"); }
__device__ __forceinline__ void pdl_trigger() { asm volatile("griddepcontrol.launch_dependents;" ::: "memory"); }

__device__ __forceinline__ float warp_sum(float v) {
#pragma unroll
    for (int o = 16; o; o >>= 1) v += __shfl_down_sync(0xffffffffu, v, o);
    return v;
}

__device__ __forceinline__ float silu(float x) { return x / (1.f + expf(-x)); }

__device__ __forceinline__ float dot4(float4 a, float4 b) {
    return a.x * b.x + a.y * b.y + a.z * b.z + a.w * b.w;
}

// ---------------- rmsnorm: out = x * rsqrt(mean(x^2)+eps) * (1+w) ----------
__global__ void rmsnorm_k(const float* __restrict__ x, const float* __restrict__ w,
                          float* __restrict__ out) {
    __shared__ float red[16];
    __shared__ float s_inv;
    pdl_wait();
    int tid = threadIdx.x;
    float ss = 0.f;
    for (int i = tid; i < HID; i += blockDim.x) { float v = x[i]; ss += v * v; }
    ss = warp_sum(ss);
    if ((tid & 31) == 0) red[tid >> 5] = ss;
    __syncthreads();
    if (tid == 0) {
        float t = 0.f;
        for (int i = 0; i < (int)(blockDim.x >> 5); i++) t += red[i];
        s_inv = rsqrtf(t / HID + 1e-6f);
    }
    __syncthreads();
    float inv = s_inv;
    for (int i = tid; i < HID; i += blockDim.x)
        out[i] = x[i] * inv * (1.f + w[i]);
    pdl_trigger();
}

// ---------------- block-per-row matvec, IT front-batched loads -------------
template <int K, int TPB, bool RES>
__global__ void __launch_bounds__(TPB) rowmv_k(
        const float* __restrict__ W, const float* __restrict__ v,
        const float* __restrict__ res, float* __restrict__ y) {
    constexpr int IT = K / 4 / TPB;
    __shared__ float red[TPB / 32];
    int r = blockIdx.x;
    const float4* Wr = (const float4*)(W + (size_t)r * K);
    float4 a[IT];
#pragma unroll
    for (int i = 0; i < IT; i++) a[i] = __ldcs(Wr + threadIdx.x + TPB * i);
    pdl_wait();
    const float4* v4 = (const float4*)v;
    float s = 0.f;
#pragma unroll
    for (int i = 0; i < IT; i++) s += dot4(a[i], __ldg(&v4[threadIdx.x + TPB * i]));
    s = warp_sum(s);
    if ((threadIdx.x & 31) == 0) red[threadIdx.x >> 5] = s;
    __syncthreads();
    if (threadIdx.x == 0) {
        float t = 0.f;
#pragma unroll
        for (int i = 0; i < TPB / 32; i++) t += red[i];
        y[r] = RES ? (res[r] + t) : t;
    }
    pdl_trigger();
}

// ---------------- in_proj matvec: 4 rows/block, 256 thr, fused conv --------
__global__ void __launch_bounds__(256) inproj_conv_k(
        const float* __restrict__ W, const float* __restrict__ v,
        const float* __restrict__ cs, const float* __restrict__ cw,
        float* __restrict__ out_conv_state) {
    __shared__ float red[4][8];
    int rb = blockIdx.x * 4;
    const float4* Wb = (const float4*)(W + (size_t)rb * HID);
    float4 a[4][2];
#pragma unroll
    for (int r = 0; r < 4; r++)
#pragma unroll
        for (int i = 0; i < 2; i++)
            a[r][i] = __ldcs(Wb + r * 512 + threadIdx.x + 256 * i);
    pdl_wait();
    const float4* v4 = (const float4*)v;
    float4 b[2];
#pragma unroll
    for (int i = 0; i < 2; i++) b[i] = __ldg(&v4[threadIdx.x + 256 * i]);
    float s[4];
#pragma unroll
    for (int r = 0; r < 4; r++) {
        s[r] = dot4(a[r][0], b[0]) + dot4(a[r][1], b[1]);
        s[r] = warp_sum(s[r]);
    }
    if ((threadIdx.x & 31) == 0) {
#pragma unroll
        for (int r = 0; r < 4; r++) red[r][threadIdx.x >> 5] = s[r];
    }
    __syncthreads();
    if (threadIdx.x < 4) {
        int r = rb + threadIdx.x;
        float tot = 0.f;
#pragma unroll
        for (int w = 0; w < 8; w++) tot += red[threadIdx.x][w];
        g_proj[r] = tot;
        if (r < QKV) {
            float c1 = cs[r * 4 + 1], c2 = cs[r * 4 + 2], c3 = cs[r * 4 + 3];
            float4 w4 = ((const float4*)cw)[r];
            float acc = c1 * w4.x + c2 * w4.y + c3 * w4.z + tot * w4.w;
            ((float4*)out_conv_state)[r] = make_float4(c1, c2, c3, tot);
            g_conv[r] = silu(acc);
        }
    }
    pdl_trigger();
}

// ---------------- gate/up fused, 2 rows/block, 256 thr ---------------------
__global__ void __launch_bounds__(256) gateup_k(
        const float* __restrict__ G, const float* __restrict__ U) {
    __shared__ float red[4][8];
    int r0 = blockIdx.x * 2;
    const float4* g0 = (const float4*)(G + (size_t)r0 * HID);
    const float4* u0 = (const float4*)(U + (size_t)r0 * HID);
    float4 ag0[2], ag1[2], au0[2], au1[2];
#pragma unroll
    for (int i = 0; i < 2; i++) {
        ag0[i] = __ldcs(g0 + threadIdx.x + 256 * i);
        ag1[i] = __ldcs(g0 + 512 + threadIdx.x + 256 * i);
        au0[i] = __ldcs(u0 + threadIdx.x + 256 * i);
        au1[i] = __ldcs(u0 + 512 + threadIdx.x + 256 * i);
    }
    pdl_wait();
    const float4* h4 = (const float4*)g_hn;
    float4 c[2];
#pragma unroll
    for (int i = 0; i < 2; i++) c[i] = __ldg(&h4[threadIdx.x + 256 * i]);
    float s[4];
    s[0] = dot4(ag0[0], c[0]) + dot4(ag0[1], c[1]);
    s[1] = dot4(ag1[0], c[0]) + dot4(ag1[1], c[1]);
    s[2] = dot4(au0[0], c[0]) + dot4(au0[1], c[1]);
    s[3] = dot4(au1[0], c[0]) + dot4(au1[1], c[1]);
#pragma unroll
    for (int j = 0; j < 4; j++) s[j] = warp_sum(s[j]);
    if ((threadIdx.x & 31) == 0) {
#pragma unroll
        for (int j = 0; j < 4; j++) red[j][threadIdx.x >> 5] = s[j];
    }
    __syncthreads();
    if (threadIdx.x < 2) {
        float tg = 0.f, tu = 0.f;
#pragma unroll
        for (int w = 0; w < 8; w++) { tg += red[threadIdx.x][w]; tu += red[2 + threadIdx.x][w]; }
        g_inter[r0 + threadIdx.x] = silu(tg) * tu;
    }
    pdl_trigger();
}

// ---------------- delta rule per head + gated rmsnorm ----------------------
// block = 1 head, 1024 threads. S staged to SMEM before pdl_wait (overlap).
__global__ void delta_k(const float* __restrict__ Sin, const float* __restrict__ A_log,
                        const float* __restrict__ dt_bias, const float* __restrict__ norm_w,
                        float* __restrict__ Sout) {
    extern __shared__ float sm[];
    float* Ssh  = sm;                    // 16384
    float* kn   = sm + KD * VD;          // 128
    float* qn   = kn + KD;               // 128
    float* dl   = qn + KD;               // 128
    float* part = dl + KD;               // 1024
    float* red  = part + 1024;           // 4

    int h   = blockIdx.x;
    int tid = threadIdx.x;
    int t   = tid & 127;
    int kg  = tid >> 7;
    int kh  = h >> 1;  // RATIO = 2

    // stage S (independent of previous kernel) BEFORE the PDL wait
    const float4* S4 = (const float4*)(Sin + (size_t)h * KD * VD);
#pragma unroll
    for (int i = 0; i < 4; i++)
        ((float4*)Ssh)[tid + 1024 * i] = S4[tid + 1024 * i];

    pdl_wait();

    float qv = 0.f, kv = 0.f, vv = 0.f;
    if (tid < 128) {
        qv = g_conv[kh * KD + t];
        kv = g_conv[NKH * KD + kh * KD + t];
        vv = g_conv[2 * NKH * KD + h * VD + t];
        float s = warp_sum(qv * qv);
        if ((t & 31) == 0) red[t >> 5] = s;
    }
    __syncthreads();
    if (tid < 128) {
        float qs = red[0] + red[1] + red[2] + red[3];
        qn[t] = qv / fmaxf(sqrtf(qs), 1e-12f);
    }
    __syncthreads();
    if (tid < 128) {
        float s = warp_sum(kv * kv);
        if ((t & 31) == 0) red[t >> 5] = s;
    }
    __syncthreads();
    if (tid < 128) {
        float ks = red[0] + red[1] + red[2] + red[3];
        kn[t] = kv / fmaxf(sqrtf(ks), 1e-12f);
    }
    __syncthreads();

    float a = g_proj[QKV + TV + h];
    float b = g_proj[QKV + TV + NVH + h];
    float beta = 1.f / (1.f + expf(-b));
    float spx = a + dt_bias[h];
    float sp = (spx > 20.f) ? spx : log1pf(expf(spx));
    float decay = expf(-expf(A_log[h]) * sp);

    // pass 1: Sk[t] = sum_k S[k,t]*kn[k], k split over 8 groups
    {
        float s = 0.f;
        int k0 = kg * 16;
#pragma unroll
        for (int k = 0; k < 16; k++) s += Ssh[(k0 + k) * VD + t] * kn[k0 + k];
        part[kg * 128 + t] = s;
    }
    __syncthreads();
    if (tid < 128) {
        float sk = 0.f;
#pragma unroll
        for (int g = 0; g < 8; g++) sk += part[g * 128 + t];
        dl[t] = vv - sk;
    }
    __syncthreads();

    // pass 2: newS (write global) + y partials
    float* So = Sout + (size_t)h * KD * VD;
    {
        float del = dl[t];
        float yp = 0.f;
        int k0 = kg * 16;
#pragma unroll
        for (int k = 0; k < 16; k++) {
            int kk = k0 + k;
            float ns = decay * Ssh[kk * VD + t] + beta * kn[kk] * del;
            So[kk * VD + t] = ns;
            yp += ns * qn[kk];
        }
        part[kg * 128 + t] = yp;
    }
    __syncthreads();

    float y = 0.f;
    if (tid < 128) {
#pragma unroll
        for (int g = 0; g < 8; g++) y += part[g * 128 + t];
        float s = warp_sum(y * y);
        if ((t & 31) == 0) red[t >> 5] = s;
    }
    __syncthreads();
    if (tid < 128) {
        float var = (red[0] + red[1] + red[2] + red[3]) / VD;
        float yn = y * rsqrtf(var + 1e-6f) * norm_w[t];
        float z = g_proj[QKV + h * VD + t];
        g_ygated[h * VD + t] = yn * silu(z);
    }
    pdl_trigger();
}

// ---------------- host-side PDL launch helper ------------------------------
template <typename F, typename... Args>
static void launch_pdl(F* func, dim3 grid, dim3 block, size_t smem, Args... args) {
    cudaLaunchAttribute attr[1] = {};
    attr[0].id = cudaLaunchAttributeProgrammaticStreamSerialization;
    attr[0].val.programmaticStreamSerializationAllowed = 1;
    cudaLaunchConfig_t cfg = {};
    cfg.gridDim = grid;
    cfg.blockDim = block;
    cfg.dynamicSmemBytes = smem;
    cfg.stream = 0;
    cfg.attrs = attr;
    cfg.numAttrs = 1;
    cudaLaunchKernelEx(&cfg, func, args...);
}

extern "C" void kernel_launch(void* const* d_in, const int* in_sizes, int n_in,
                              void* d_out, int out_size) {
    const float* x          = (const float*)d_in[0];
    const float* conv_state = (const float*)d_in[1];
    const float* ssm_state  = (const float*)d_in[2];
    const float* in_ln_w    = (const float*)d_in[3];
    const float* in_proj_w  = (const float*)d_in[4];
    const float* conv_w     = (const float*)d_in[5];
    const float* A_log      = (const float*)d_in[6];
    const float* dt_bias    = (const float*)d_in[7];
    const float* norm_w     = (const float*)d_in[8];
    const float* out_proj_w = (const float*)d_in[9];
    const float* post_ln_w  = (const float*)d_in[10];
    const float* gate_w     = (const float*)d_in[11];
    const float* up_w       = (const float*)d_in[12];
    const float* down_w     = (const float*)d_in[13];

    float* out        = (float*)d_out;
    float* out_x      = out;                       // 2048
    float* out_conv   = out + HID;                 // 32768
    float* out_ssm    = out + HID + QKV * CK;      // 524288

    float *p_h, *p_x1, *p_hn, *p_inter, *p_yg;
    cudaGetSymbolAddress((void**)&p_h,     g_h);
    cudaGetSymbolAddress((void**)&p_x1,    g_x1);
    cudaGetSymbolAddress((void**)&p_hn,    g_hn);
    cudaGetSymbolAddress((void**)&p_inter, g_inter);
    cudaGetSymbolAddress((void**)&p_yg,    g_ygated);

    const int ROWS_INPROJ = QKV + TV + 2 * NVH;  // 12352
    const int DELTA_SMEM = (KD * VD + 3 * KD + 1024 + 16) * sizeof(float);  // ~70KB
    cudaFuncSetAttribute(delta_k, cudaFuncAttributeMaxDynamicSharedMemorySize, DELTA_SMEM);

    // 1. h = rmsnorm(x, in_ln_w)
    launch_pdl(rmsnorm_k, 1, 512, 0, x, in_ln_w, p_h);
    // 2. proj = in_proj_w @ h  (12352 x 2048), fused conv update, 4 rows/block
    launch_pdl(inproj_conv_k, ROWS_INPROJ / 4, 256, 0,
               in_proj_w, (const float*)p_h, conv_state, conv_w, out_conv);
    // 3. per-head delta rule + gated rmsnorm -> g_ygated, new ssm state
    launch_pdl(delta_k, NVH, 1024, (size_t)DELTA_SMEM,
               ssm_state, A_log, dt_bias, norm_w, out_ssm);
    // 4. x1 = x + out_proj_w @ y_gated   (2048 x 4096), 8 loads/thread
    launch_pdl(rowmv_k<TV, 128, true>, HID, 128, 0,
               out_proj_w, (const float*)p_yg, x, p_x1);
    // 5. hn = rmsnorm(x1, post_ln_w)
    launch_pdl(rmsnorm_k, 1, 512, 0, (const float*)p_x1, post_ln_w, p_hn);
    // 6. inter = silu(gate_w@hn) * (up_w@hn), 2 rows/block, 256 thr
    launch_pdl(gateup_k, INTER / 2, 256, 0, gate_w, up_w);
    // 7. x_out = x1 + down_w @ inter   (2048 x 8192), 8 loads/thread
    launch_pdl(rowmv_k<INTER, 256, true>, HID, 256, 0,
               down_w, (const float*)p_inter, (const float*)p_x1, out_x);
}